// round 11
// baseline (speedup 1.0000x reference)
#include <cuda_runtime.h>
#include <math.h>

// Problem constants (fixed by the dataset)
#define L_DIM  16384
#define H_DIM  1024

// R11: R10's no-halo carry-exchange architecture with a FIXED sync protocol.
//   Block = CHUNK=32 rows x 128 channels (1 ch/thread). Each block scans its
//   own rows from zero, publishes per-channel partials, and builds its carry
//   from the 3 predecessor chunks:
//     carry_c = P_{c-1} + A^32*P_{c-2} + A^64*P_{c-3}   (A^96 ~ 5e-10)
//   R10's bug: every thread paid a MEMBAR.GPU + atomicAdd + 3 volatile DRAM
//   spin loops (~16us of pure sync). R11 uses decoupled-lookback discipline:
//   one fence + one flag store per block (tid 0, after __syncthreads; the
//   barrier + cumulative fence covers all threads' partial stores), and only
//   NPRED poller threads spin. Loads are batch-pipelined (8 rows) to avoid
//   front-batched L1tex queue spread.
#define CHUNK  32
#define NCHUNK (L_DIM / CHUNK)    // 512
#define TPB    128
#define GROUPS (H_DIM / TPB)      // 8
#define NFLAGS (NCHUNK * GROUPS)  // 4096
#define NPRED  3
#define BATCH  8
#define NB     (CHUNK / BATCH)    // 4

__device__ float        g_partial[NCHUNK * H_DIM];   // per-chunk per-channel partials
__device__ int          g_flag[NFLAGS];              // 0 = pending, 1 = published
__device__ unsigned int g_ticket;                    // block scheduling ticket

__global__ void zero_flags_kernel() {
    int i = blockIdx.x * blockDim.x + threadIdx.x;
    if (i < NFLAGS) g_flag[i] = 0;
    if (i == 0)     g_ticket  = 0u;
}

__global__ __launch_bounds__(TPB, 8)
void LI_scan_kernel(const float* __restrict__ x,
                    const float* __restrict__ tau,
                    float* __restrict__ out) {
    // Ticket -> (chunk, group): chunk increases with arrival order, so a
    // block's predecessors (chunk-p, same group) always started earlier.
    __shared__ unsigned int sT;
    if (threadIdx.x == 0) sT = atomicAdd(&g_ticket, 1u);
    __syncthreads();
    const int chunk = (int)(sT / GROUPS);
    const int grp   = (int)(sT % GROUPS);

    const int   ch = grp * TPB + threadIdx.x;
    const float A  = expf(tau[ch]);
    const int base = chunk * CHUNK * H_DIM + ch;     // 32-bit: L*H = 2^24

    // ---- Load + local scan, batch-pipelined (prefetch next 8 while scanning) ----
    float v[CHUNK];
#pragma unroll
    for (int j = 0; j < BATCH; ++j)
        v[j] = x[base + j * H_DIM];
    float a = 0.f;
#pragma unroll
    for (int b = 0; b < NB; ++b) {
        if (b + 1 < NB) {
#pragma unroll
            for (int j = 0; j < BATCH; ++j)
                v[(b + 1) * BATCH + j] = x[base + ((b + 1) * BATCH + j) * H_DIM];
        }
#pragma unroll
        for (int j = 0; j < BATCH; ++j) {
            a = fmaf(A, a, v[b * BATCH + j]);
            v[b * BATCH + j] = a;                    // keep local inclusive scan
        }
    }

    // ---- Publish: plain coalesced store; ONE fence + flag store per block ----
    g_partial[chunk * H_DIM + ch] = a;
    __syncthreads();                                 // all partial stores done (block scope)
    if (threadIdx.x == 0) {
        __threadfence();                             // cumulative: covers whole block's stores
        *(volatile int*)&g_flag[chunk * GROUPS + grp] = 1;
    }

    // A^CHUNK via 5 squarings (CHUNK = 32 = 2^5)
    float Ac = A;
#pragma unroll
    for (int q = 0; q < 5; ++q) Ac *= Ac;

    // ---- Wait for predecessors: only NPRED poller threads spin ----
    const int np = chunk < NPRED ? chunk : NPRED;
    if (threadIdx.x < np) {
        volatile int* f = &g_flag[(chunk - 1 - threadIdx.x) * GROUPS + grp];
        while (*f == 0) { __nanosleep(32); }
        __threadfence();                             // acquire (cumulative)
    }
    __syncthreads();                                 // broadcast "preds ready" to block

    // ---- Carry: farthest-first fold over predecessor partials ----
    float carry = 0.f;
#pragma unroll
    for (int p = NPRED; p >= 1; --p)
        if (p <= np)
            carry = fmaf(Ac, carry, g_partial[(chunk - p) * H_DIM + ch]);

    // ---- Fixup + store: out[j] = local[j] + A^(j+1) * carry ----
    float pc = carry;
#pragma unroll
    for (int j = 0; j < CHUNK; ++j) {
        pc *= A;
        __stcs(out + base + j * H_DIM, v[j] + pc);   // streaming store
    }
}

extern "C" void kernel_launch(void* const* d_in, const int* in_sizes, int n_in,
                              void* d_out, int out_size) {
    const float* x   = (const float*)d_in[0];   // (L, H) fp32
    const float* tau = (const float*)d_in[1];   // (H,)   fp32
    float*       out = (float*)d_out;           // (L, H) fp32

    zero_flags_kernel<<<(NFLAGS + 255) / 256, 256>>>();

    dim3 grid(NCHUNK, GROUPS);                  // (512, 8) = 4096 blocks
    LI_scan_kernel<<<grid, TPB>>>(x, tau, out);
}

// round 12
// speedup vs baseline: 2.2931x; 2.2931x over previous
#include <cuda_runtime.h>
#include <math.h>

// Problem constants (fixed by the dataset)
#define L_DIM 16384
#define H_DIM 1024

// R12: consolidation of the halo family at minimum traffic.
//   Scalar mapping: block = CHUNK=128 rows x 128 channels, TPB=128,
//   GROUPS=8 -> grid (128,8) = 1024 blocks (~7/SM, occ ~44%).
//   K=32 halo (threshold 2e-3; measured rel_err 1.3e-4 in R8, 7.6x margin)
//   amortized over CHUNK=128 -> read amplification 1.25x -> 80MB reads +
//   64MB writes = 144MB total L2 traffic (R7: 168MB). R5 proved the longer
//   serial chain (160 rows) is free; R9's 4-deep register pipeline provides
//   24-row prefetch depth at ~55 regs (8 blocks/SM budget).
//   Cross-block sync approaches (R6/R10/R11) all regressed -- abandoned.
#define CHUNK  128
#define GROUPS 8          // H / TPB
#define TPB    128
#define BATCH  8          // rows per buffer
#define OHD    (BATCH * H_DIM)

__device__ __forceinline__ void loadB(float v[BATCH], const float* px, int off) {
#pragma unroll
    for (int j = 0; j < BATCH; ++j)
        v[j] = px[off + j * H_DIM];     // 8 back-to-back LDG.32 (128B/warp coalesced)
}

__device__ __forceinline__ void procB(const float v[BATCH], float A, float& acc,
                                      float* po, int off, bool store) {
#pragma unroll
    for (int j = 0; j < BATCH; ++j) {
        acc = fmaf(A, acc, v[j]);
        if (store)   // evict-first store: don't let out[] evict x[] halo lines from L2
            __stcs(po + off + j * H_DIM, acc);
    }
}

// 8 blocks/SM (1024 threads) -> 64-reg/thread budget; 4 buffers take 32.
__global__ __launch_bounds__(TPB, 8)
void LI_scan_kernel(const float* __restrict__ x,
                    const float* __restrict__ tau,
                    float* __restrict__ out) {
    const int chunk_start = blockIdx.x * CHUNK;
    const int ch          = blockIdx.y * TPB + threadIdx.x;

    // Per-channel decay A = exp(tau)
    const float A = expf(tau[ch]);

    // Runtime halo length K: smallest K with A^K < 2e-3 (measured rel_err at
    // this threshold: 1.3e-4 -- 7.6x under the 1e-3 tolerance). Rounded up to
    // a BATCH multiple. Falls back to exact full prefix if A ~ 1.
    int K;
    if (!(A < 0.999999f)) {
        K = chunk_start;                       // no usable decay: exact prefix
    } else if (A <= 1e-12f) {
        K = 0;
    } else {
        int ki = (int)ceilf(logf(2e-3f) / logf(A));
        if (ki < 0) ki = 0;
        ki = (ki + BATCH - 1) & ~(BATCH - 1);  // round up to multiple of BATCH
        K = ki < chunk_start ? ki : chunk_start;  // chunk_start % BATCH == 0
    }

    // Block-uniform K (keeps pipeline structure aligned across the block)
    __shared__ int sK;
    if (threadIdx.x == 0) sK = 0;
    __syncthreads();
    atomicMax(&sK, K);
    __syncthreads();
    K = sK;

    const float* px = x + ch;
    float*       po = out + ch;

    float acc = 0.f;

    // ---- Fused halo + main loop, 4-deep software pipeline ----
    // Rows [chunk_start-K, chunk_start) warm up acc (no stores);
    // rows [chunk_start, chunk_start+CHUNK) also store. K and CHUNK are
    // multiples of BATCH, so each batch is uniformly halo or main.
    // 32-bit element offsets: L*H = 2^24 fits comfortably.
    int off        = (chunk_start - K) * H_DIM;  // current batch offset
    const int off0 = chunk_start * H_DIM;        // first storing offset
    const int nb   = (K + CHUNK) / BATCH;        // 16..20

    float v0[BATCH], v1[BATCH], v2[BATCH], v3[BATCH];
    loadB(v0, px, off);
    if (nb > 1) loadB(v1, px, off + OHD);
    if (nb > 2) loadB(v2, px, off + 2 * OHD);
    int b = 0;
    while (true) {
        if (b + 3 < nb) loadB(v3, px, off + 3 * OHD);   // prefetch 3 batches ahead
        procB(v0, A, acc, po, off, off >= off0);
        off += OHD; if (++b >= nb) break;
        if (b + 3 < nb) loadB(v0, px, off + 3 * OHD);
        procB(v1, A, acc, po, off, off >= off0);
        off += OHD; if (++b >= nb) break;
        if (b + 3 < nb) loadB(v1, px, off + 3 * OHD);
        procB(v2, A, acc, po, off, off >= off0);
        off += OHD; if (++b >= nb) break;
        if (b + 3 < nb) loadB(v2, px, off + 3 * OHD);
        procB(v3, A, acc, po, off, off >= off0);
        off += OHD; if (++b >= nb) break;
    }
}

extern "C" void kernel_launch(void* const* d_in, const int* in_sizes, int n_in,
                              void* d_out, int out_size) {
    const float* x   = (const float*)d_in[0];   // (L, H) fp32
    const float* tau = (const float*)d_in[1];   // (H,)   fp32
    float*       out = (float*)d_out;           // (L, H) fp32

    dim3 grid(L_DIM / CHUNK, GROUPS);           // (128, 8) = 1024 blocks
    LI_scan_kernel<<<grid, TPB>>>(x, tau, out);
}

// round 13
// speedup vs baseline: 2.6501x; 1.1557x over previous
#include <cuda_runtime.h>
#include <math.h>

// Problem constants (fixed by the dataset)
#define L_DIM 16384
#define H_DIM 1024

// R13: timed-best config (R7: float2, CHUNK=64, GROUPS=4, TPB=128,
// 8 blocks/SM, double-buffered 8-row batches) with the one knob that has a
// measured positive effect: halo K 40 -> 32 (threshold 2e-3; R8 measured
// rel_err 1.32e-4 at this threshold = 7.6x margin under 1e-3).
// Traffic 168 -> 160 MB, per-warp serial chain 104 -> 96 rows.
// Mapped-out dead ends: cross-block sync (R6/R10/R11 regressed), cp.async
// ring (R8), deeper register pipeline (R9 neutral), CHUNK=128 scalar (R12).
#define CHUNK  64
#define GROUPS 4          // H / 256
#define TPB    128
#define BATCH  8          // outstanding LDG.64 per thread per buffer

__device__ __forceinline__ float2 ld2(const float* p) {
    return *reinterpret_cast<const float2*>(p);
}

__device__ __forceinline__ void loadB(float2 v[BATCH], const float* px, int off) {
#pragma unroll
    for (int j = 0; j < BATCH; ++j)
        v[j] = ld2(px + off + j * H_DIM);   // BATCH back-to-back LDG.64
}

__device__ __forceinline__ void procB(const float2 v[BATCH], float2 A, float2& acc,
                                      float* po, int off, bool store) {
#pragma unroll
    for (int j = 0; j < BATCH; ++j) {
        acc.x = fmaf(A.x, acc.x, v[j].x);
        acc.y = fmaf(A.y, acc.y, v[j].y);
        if (store)   // evict-first store: don't let out[] evict x[] halo lines from L2
            __stcs(reinterpret_cast<float2*>(po + off + j * H_DIM), acc);
    }
}

// 8 blocks/SM (1024 threads) -> 64-reg/thread budget. Buffers are 32 regs.
__global__ __launch_bounds__(TPB, 8)
void LI_scan_kernel(const float* __restrict__ x,
                    const float* __restrict__ tau,
                    float* __restrict__ out) {
    const int chunk_start = blockIdx.x * CHUNK;
    const int ch          = (blockIdx.y * TPB + threadIdx.x) * 2;

    // Per-channel decay A = exp(tau)
    float2 t = ld2(tau + ch);
    float2 A;
    A.x = expf(t.x); A.y = expf(t.y);

    // Runtime halo length K: smallest K with Amax^K < 2e-3 (measured rel_err
    // at this threshold: 1.32e-4, 7.6x under the 1e-3 tolerance). Rounded up
    // to a BATCH multiple. Falls back to exact full prefix if A ~ 1.
    float amax = fmaxf(A.x, A.y);
    int K;
    if (!(amax < 0.999999f)) {
        K = chunk_start;                       // no usable decay: exact prefix
    } else if (amax <= 1e-12f) {
        K = 0;
    } else {
        int ki = (int)ceilf(logf(2e-3f) / logf(amax));
        if (ki < 0) ki = 0;
        ki = (ki + BATCH - 1) & ~(BATCH - 1);  // round up to multiple of BATCH
        K = ki < chunk_start ? ki : chunk_start;  // chunk_start % BATCH == 0
    }

    // Block-uniform K (keeps batch loop structure aligned across the block)
    __shared__ int sK;
    if (threadIdx.x == 0) sK = 0;
    __syncthreads();
    atomicMax(&sK, K);
    __syncthreads();
    K = sK;

    const float* px = x + ch;
    float*       po = out + ch;

    float2 acc = make_float2(0.f, 0.f);

    // ---- Fused halo + main loop, software-pipelined (double buffer) ----
    // Rows [chunk_start-K, chunk_start) warm up acc (no stores);
    // rows [chunk_start, chunk_start+CHUNK) also store. K and CHUNK are both
    // multiples of BATCH, so each batch is uniformly halo or main.
    // 32-bit element offsets: L*H = 2^24 fits comfortably.
    int off        = (chunk_start - K) * H_DIM;  // current batch offset
    const int off0 = chunk_start * H_DIM;        // first storing offset
    const int nb   = (K + CHUNK) / BATCH;        // >= CHUNK/BATCH = 8

    float2 v0[BATCH], v1[BATCH];
    loadB(v0, px, off);
    int b = 0;
    while (true) {
        if (b + 1 < nb) loadB(v1, px, off + BATCH * H_DIM);  // prefetch next batch
        procB(v0, A, acc, po, off, off >= off0);
        off += BATCH * H_DIM; if (++b >= nb) break;
        if (b + 1 < nb) loadB(v0, px, off + BATCH * H_DIM);  // prefetch next batch
        procB(v1, A, acc, po, off, off >= off0);
        off += BATCH * H_DIM; if (++b >= nb) break;
    }
}

extern "C" void kernel_launch(void* const* d_in, const int* in_sizes, int n_in,
                              void* d_out, int out_size) {
    const float* x   = (const float*)d_in[0];   // (L, H) fp32
    const float* tau = (const float*)d_in[1];   // (H,)   fp32
    float*       out = (float*)d_out;           // (L, H) fp32

    dim3 grid(L_DIM / CHUNK, GROUPS);           // (256, 4) = 1024 blocks
    LI_scan_kernel<<<grid, TPB>>>(x, tau, out);
}